// round 10
// baseline (speedup 1.0000x reference)
#include <cuda_runtime.h>
#include <cuda_fp16.h>
#include <cstdint>

#define BATCH 2
#define SEQ   8192
#define CDIM  1024
#define HDIM  64
#define NROWS (BATCH * SEQ)   // 16384
#define QKVW  (3 * HDIM)      // 192

// ---- device scratch (no allocations) --------------------------------------
__device__ __half g_wh[QKVW * CDIM];             // W^T fp16  [192][1024]

// ---- helpers ----------------------------------------------------------------
__device__ __forceinline__ uint32_t smem_u32(const void* p) {
    uint32_t a;
    asm("{ .reg .u64 t; cvta.to.shared.u64 t, %1; cvt.u32.u64 %0, t; }"
        : "=r"(a) : "l"(p));
    return a;
}
__device__ __forceinline__ void ldm_x4(uint32_t* r, uint32_t addr) {
    asm volatile("ldmatrix.sync.aligned.m8n8.x4.shared.b16 {%0,%1,%2,%3}, [%4];"
        : "=r"(r[0]), "=r"(r[1]), "=r"(r[2]), "=r"(r[3]) : "r"(addr));
}
__device__ __forceinline__ void mma_f16(float* c, const uint32_t* a, const uint32_t* b) {
    asm volatile("mma.sync.aligned.m16n8k16.row.col.f32.f16.f16.f32 "
        "{%0,%1,%2,%3}, {%4,%5,%6,%7}, {%8,%9}, {%0,%1,%2,%3};"
        : "+f"(c[0]), "+f"(c[1]), "+f"(c[2]), "+f"(c[3])
        : "r"(a[0]), "r"(a[1]), "r"(a[2]), "r"(a[3]), "r"(b[0]), "r"(b[1]));
}
#define CP_ASYNC16(sm, gm) \
    asm volatile("cp.async.cg.shared.global [%0], [%1], 16;" :: "r"(sm), "l"(gm) : "memory")
#define CP_COMMIT() asm volatile("cp.async.commit_group;" ::: "memory")
#define CP_WAIT0()  asm volatile("cp.async.wait_group 0;" ::: "memory")

__device__ __forceinline__ uint32_t pack_h2(float a, float b) {
    __half2 t = __floats2half2_rn(a, b);
    return *reinterpret_cast<uint32_t*>(&t);
}

// ---------------------------------------------------------------------------
// Pre-pass: W fp32 [1024][64] x3  ->  W^T fp16 [192][1024]
// ---------------------------------------------------------------------------
__global__ __launch_bounds__(256)
void conv_w(const float* __restrict__ Wq,
            const float* __restrict__ Wk,
            const float* __restrict__ Wv) {
    __shared__ float ts[16][65];
    const int mat = blockIdx.x >> 6;          // 0..2
    const int k0  = (blockIdx.x & 63) * 16;   // k tile
    const float* W = (mat == 0) ? Wq : ((mat == 1) ? Wk : Wv);
    const int tid = threadIdx.x;

    const int ln = tid & 63, lk = tid >> 6;
    #pragma unroll
    for (int i = 0; i < 4; i++)
        ts[lk + i * 4][ln] = W[(size_t)(k0 + lk + i * 4) * 64 + ln];
    __syncthreads();

    const int n = tid >> 2, kq = (tid & 3) * 4;
    __half* hd = g_wh + (size_t)(mat * 64 + n) * CDIM + k0 + kq;
    __half2 a = __floats2half2_rn(ts[kq + 0][n], ts[kq + 1][n]);
    __half2 b = __floats2half2_rn(ts[kq + 2][n], ts[kq + 3][n]);
    *reinterpret_cast<__half2*>(hd)     = a;
    *reinterpret_cast<__half2*>(hd + 2) = b;
}

// ---------------------------------------------------------------------------
// Fused QKV GEMM + windowed attention.
// 112 queries per CTA; A tile = 128 rows [m0-16, m0+112) clamped. N=192. BK=64.
// grid = 147. 16 warps (512 thr): 4m x 4n, warp tile 32x48, acc 48 regs.
// ---------------------------------------------------------------------------
#define MTQ  112              // queries per CTA
#define MA   128              // A tile rows (16 halo + 112)
#define BK   64
#define NCH  (CDIM / BK)      // 16 chunks
#define NT   512              // threads
#define SA   72               // A/B smem row stride in halfs
#define OFF_A  0
#define OFF_B  (MA * SA * 2)                       // 18432
#define STAGE  (OFF_B + QKVW * SA * 2)             // 46080
// attention overlay (floats): qs[112*66] | ks[128*66] | vs[128*66]
#define ATT_FLOATS ((MTQ + MA + MA) * 66)          // 24288
#define FUSED_SMEM (ATT_FLOATS * 4 > 2 * STAGE ? ATT_FLOATS * 4 : 2 * STAGE)  // 97152

__global__ __launch_bounds__(NT, 1)
void qkv_attn(const float* __restrict__ x, float* __restrict__ out) {
    extern __shared__ char sm[];
    const uint32_t smb = smem_u32(sm);
    float* const sp = reinterpret_cast<float*>(sm);
    float* const qs = sp;                 // [112][66]
    float* const ks = sp + MTQ * 66;      // [128][66]
    float* const vs = ks + MA * 66;       // [128][66]

    const int tid  = threadIdx.x;
    const int wid  = tid >> 5;
    const int lane = tid & 31;
    const int wmm  = wid >> 2;       // 0..3  (m-warp, 32 rows)
    const int wn   = wid & 3;        // 0..3  (n-warp, 48 cols)
    const int m0   = blockIdx.x * MTQ;

    float acc[2][6][4];
    #pragma unroll
    for (int mt = 0; mt < 2; mt++)
        #pragma unroll
        for (int nt = 0; nt < 6; nt++)
            #pragma unroll
            for (int q = 0; q < 4; q++) acc[mt][nt][q] = 0.f;

    const int a_row  = (lane & 15);
    const int a_col  = (lane >> 4) * 8;
    const int b_rowo = ((lane >> 4) << 3) + (lane & 7);
    const int b_col  = ((lane >> 3) & 1) * 8;

    // x loader: 128 rows x 16 float4 = 2048 -> 4 per thread
    float4 xf[4];
    auto load_x = [&](int k0) {
        #pragma unroll
        for (int l = 0; l < 4; l++) {
            int idx = l * NT + tid;
            int row = idx >> 4, c4 = idx & 15;
            int gr = m0 - 16 + row;
            gr = gr < 0 ? 0 : (gr >= NROWS ? NROWS - 1 : gr);
            xf[l] = *reinterpret_cast<const float4*>(
                x + (size_t)gr * CDIM + k0 + c4 * 4);
        }
    };
    auto store_x = [&](char* stp) {
        #pragma unroll
        for (int l = 0; l < 4; l++) {
            int idx = l * NT + tid;
            int row = idx >> 4, c4 = idx & 15;
            uint2 hp = make_uint2(pack_h2(xf[l].x, xf[l].y), pack_h2(xf[l].z, xf[l].w));
            *reinterpret_cast<uint2*>(stp + OFF_A + (uint32_t)(row * SA + c4 * 4) * 2) = hp;
        }
    };
    // B loader: 192 rows x 8 16B-units = 1536 -> 3 per thread
    auto issue_b = [&](uint32_t stn, int k0) {
        #pragma unroll
        for (int l = 0; l < 3; l++) {
            int idx = l * NT + tid;
            int n = idx >> 3, u = idx & 7;
            uint32_t so = (uint32_t)(n * SA) * 2 + u * 16;
            CP_ASYNC16(stn + OFF_B + so, g_wh + (size_t)n * CDIM + k0 + u * 8);
        }
        CP_COMMIT();
    };

    // ---- prologue ----
    load_x(0);
    issue_b(smb, 0);
    store_x(sm);
    CP_WAIT0();
    __syncthreads();

    for (int c = 0; c < NCH; c++) {
        const int s = c & 1;
        const uint32_t st = smb + s * STAGE;
        const bool more = (c + 1 < NCH);

        if (more) {
            load_x((c + 1) * BK);
            issue_b(smb + (s ^ 1) * STAGE, (c + 1) * BK);
        }

        #pragma unroll
        for (int ksp = 0; ksp < 4; ksp++) {
            const int k0h = ksp * 16;
            uint32_t ah[2][4], bf[3][4];
            #pragma unroll
            for (int mt = 0; mt < 2; mt++) {
                uint32_t ao = (uint32_t)((wmm * 32 + mt * 16 + a_row) * SA + k0h + a_col) * 2;
                ldm_x4(ah[mt], st + OFF_A + ao);
            }
            #pragma unroll
            for (int g = 0; g < 3; g++) {
                uint32_t bo = (uint32_t)((wn * 48 + g * 16 + b_rowo) * SA + k0h + b_col) * 2;
                ldm_x4(bf[g], st + OFF_B + bo);
            }
            #pragma unroll
            for (int mt = 0; mt < 2; mt++)
                #pragma unroll
                for (int g = 0; g < 3; g++) {
                    mma_f16(acc[mt][2 * g],     ah[mt], &bf[g][0]);
                    mma_f16(acc[mt][2 * g + 1], ah[mt], &bf[g][2]);
                }
        }

        if (more) {
            store_x(sm + (s ^ 1) * STAGE);
            CP_WAIT0();
            __syncthreads();
        }
    }

    // ---- scatter fragments into attention smem layout (scalar stores) ----
    __syncthreads();
    {
        const int grp = lane >> 2, tig = lane & 3;
        #pragma unroll
        for (int mt = 0; mt < 2; mt++) {
            #pragma unroll
            for (int nt = 0; nt < 6; nt++) {
                const int col = wn * 48 + nt * 8 + tig * 2;
                const int cm = col & 63;
                const int ho = (cm < 32) ? cm : cm + 1;    // padded half offset
                #pragma unroll
                for (int half = 0; half < 2; half++) {
                    const int row = wmm * 32 + mt * 16 + grp + half * 8;
                    float v0 = acc[mt][nt][half * 2];
                    float v1 = acc[mt][nt][half * 2 + 1];
                    if (col < 64) {
                        if (row >= 16) {
                            float* p = qs + (row - 16) * 66 + ho;
                            p[0] = v0; p[1] = v1;
                        }
                    } else if (col < 128) {
                        float* p = ks + row * 66 + ho;
                        p[0] = v0; p[1] = v1;
                    } else {
                        float* p = vs + row * 66 + ho;
                        p[0] = v0; p[1] = v1;
                    }
                }
            }
        }
    }
    __syncthreads();

    // ---- attention: warps 0..6, 16 queries x 2 dim-halves per warp ----
    if (wid < 7) {
        const int qi = wid * 16 + (lane & 15);     // 0..111
        const int h  = lane >> 4;
        const int d0 = h * 32;
        const int gq = m0 + qi;                    // global query row
        const int i  = gq & (SEQ - 1);             // batch-local position

        float q[32];
        {
            const float* qp = qs + qi * 66 + h * 33;
            #pragma unroll
            for (int cc = 0; cc < 32; cc++) q[cc] = qp[cc];
        }

        float sc[17];
        float mx = -1e30f;
        #pragma unroll
        for (int t = 0; t < 17; t++) {
            const float* kr = ks + (qi + t) * 66 + h * 33;
            float p0 = 0.f, p1 = 0.f, p2 = 0.f, p3 = 0.f;
            #pragma unroll
            for (int cc = 0; cc < 32; cc += 4) {
                p0 = fmaf(q[cc + 0], kr[cc + 0], p0);
                p1 = fmaf(q[cc + 1], kr[cc + 1], p1);
                p2 = fmaf(q[cc + 2], kr[cc + 2], p2);
                p3 = fmaf(q[cc + 3], kr[cc + 3], p3);
            }
            float p = (p0 + p1) + (p2 + p3);
            p += __shfl_xor_sync(0xffffffffu, p, 16);
            float d = (i - 16 + t >= 0) ? p * 0.125f : -1e30f;
            sc[t] = d;
            mx = fmaxf(mx, d);
        }

        float den = 0.f;
        #pragma unroll
        for (int t = 0; t < 17; t++) { sc[t] = __expf(sc[t] - mx); den += sc[t]; }
        const float inv = 1.0f / den;

        if (gq < NROWS) {
            float* op = out + (size_t)gq * HDIM + d0;
            #pragma unroll
            for (int cb = 0; cb < 32; cb += 4) {
                float a0 = 0.f, a1 = 0.f, a2 = 0.f, a3 = 0.f;
                #pragma unroll
                for (int t = 0; t < 17; t++) {
                    const float* vr = vs + (qi + t) * 66 + h * 33 + cb;
                    a0 = fmaf(sc[t], vr[0], a0);
                    a1 = fmaf(sc[t], vr[1], a1);
                    a2 = fmaf(sc[t], vr[2], a2);
                    a3 = fmaf(sc[t], vr[3], a3);
                }
                *reinterpret_cast<float4*>(op + cb) =
                    make_float4(a0 * inv, a1 * inv, a2 * inv, a3 * inv);
            }
        }
    }
}

// ---------------------------------------------------------------------------
extern "C" void kernel_launch(void* const* d_in, const int* in_sizes, int n_in,
                              void* d_out, int out_size)
{
    const float* x  = (const float*)d_in[0];
    const float* Wq = (const float*)d_in[1];
    const float* Wk = (const float*)d_in[2];
    const float* Wv = (const float*)d_in[3];
    float* out = (float*)d_out;

    cudaFuncSetAttribute(qkv_attn, cudaFuncAttributeMaxDynamicSharedMemorySize, FUSED_SMEM);

    const int grid = (NROWS + MTQ - 1) / MTQ;   // 147
    conv_w<<<192, 256>>>(Wq, Wk, Wv);
    qkv_attn<<<grid, NT, FUSED_SMEM>>>(x, out);
}

// round 11
// speedup vs baseline: 1.0060x; 1.0060x over previous
#include <cuda_runtime.h>
#include <cuda_fp16.h>
#include <cstdint>

#define BATCH 2
#define SEQ   8192
#define CDIM  1024
#define HDIM  64
#define NROWS (BATCH * SEQ)   // 16384
#define QKVW  (3 * HDIM)      // 192

// ---- device scratch (no allocations) --------------------------------------
__device__ __half g_wh[QKVW * CDIM];             // W^T fp16  [192][1024]

// ---- helpers ----------------------------------------------------------------
__device__ __forceinline__ uint32_t smem_u32(const void* p) {
    uint32_t a;
    asm("{ .reg .u64 t; cvta.to.shared.u64 t, %1; cvt.u32.u64 %0, t; }"
        : "=r"(a) : "l"(p));
    return a;
}
__device__ __forceinline__ void ldm_x4(uint32_t* r, uint32_t addr) {
    asm volatile("ldmatrix.sync.aligned.m8n8.x4.shared.b16 {%0,%1,%2,%3}, [%4];"
        : "=r"(r[0]), "=r"(r[1]), "=r"(r[2]), "=r"(r[3]) : "r"(addr));
}
__device__ __forceinline__ void mma_f16(float* c, const uint32_t* a, const uint32_t* b) {
    asm volatile("mma.sync.aligned.m16n8k16.row.col.f32.f16.f16.f32 "
        "{%0,%1,%2,%3}, {%4,%5,%6,%7}, {%8,%9}, {%0,%1,%2,%3};"
        : "+f"(c[0]), "+f"(c[1]), "+f"(c[2]), "+f"(c[3])
        : "r"(a[0]), "r"(a[1]), "r"(a[2]), "r"(a[3]), "r"(b[0]), "r"(b[1]));
}
#define CP_ASYNC16(sm, gm) \
    asm volatile("cp.async.cg.shared.global [%0], [%1], 16;" :: "r"(sm), "l"(gm) : "memory")
#define CP_COMMIT() asm volatile("cp.async.commit_group;" ::: "memory")
#define CP_WAIT0()  asm volatile("cp.async.wait_group 0;" ::: "memory")

__device__ __forceinline__ uint32_t pack_h2(float a, float b) {
    __half2 t = __floats2half2_rn(a, b);
    return *reinterpret_cast<uint32_t*>(&t);
}

// ---------------------------------------------------------------------------
// Pre-pass: W fp32 [1024][64] x3  ->  W^T fp16 [192][1024]
// ---------------------------------------------------------------------------
__global__ __launch_bounds__(256)
void conv_w(const float* __restrict__ Wq,
            const float* __restrict__ Wk,
            const float* __restrict__ Wv) {
    __shared__ float ts[16][65];
    const int mat = blockIdx.x >> 6;          // 0..2
    const int k0  = (blockIdx.x & 63) * 16;   // k tile
    const float* W = (mat == 0) ? Wq : ((mat == 1) ? Wk : Wv);
    const int tid = threadIdx.x;

    const int ln = tid & 63, lk = tid >> 6;
    #pragma unroll
    for (int i = 0; i < 4; i++)
        ts[lk + i * 4][ln] = W[(size_t)(k0 + lk + i * 4) * 64 + ln];
    __syncthreads();

    const int n = tid >> 2, kq = (tid & 3) * 4;
    __half* hd = g_wh + (size_t)(mat * 64 + n) * CDIM + k0 + kq;
    __half2 a = __floats2half2_rn(ts[kq + 0][n], ts[kq + 1][n]);
    __half2 b = __floats2half2_rn(ts[kq + 2][n], ts[kq + 3][n]);
    *reinterpret_cast<__half2*>(hd)     = a;
    *reinterpret_cast<__half2*>(hd + 2) = b;
}

// ---------------------------------------------------------------------------
// Fused QKV GEMM + windowed attention.
// 112 queries per CTA; A tile = 128 rows [m0-16, m0+112) clamped. N=192. BK=64.
// grid = 147. 8 warps (256 thr): 2m x 4n, warp tile 64x48, acc 96 regs.
// Wide warp tiles -> 1.17 ldmatrix-matrices per MMA (was 1.67).
// ---------------------------------------------------------------------------
#define MTQ  112              // queries per CTA
#define MA   128              // A tile rows (16 halo + 112)
#define BK   64
#define NCH  (CDIM / BK)      // 16 chunks
#define NT   256              // threads
#define SA   72               // A/B smem row stride in halfs
#define OFF_A  0
#define OFF_B  (MA * SA * 2)                       // 18432
#define STAGE  (OFF_B + QKVW * SA * 2)             // 46080
// attention overlay (floats): qs[112*66] | ks[128*66] | vs[128*66]
#define ATT_FLOATS ((MTQ + MA + MA) * 66)          // 24288
#define FUSED_SMEM (ATT_FLOATS * 4 > 2 * STAGE ? ATT_FLOATS * 4 : 2 * STAGE)  // 97152

__global__ __launch_bounds__(NT, 1)
void qkv_attn(const float* __restrict__ x, float* __restrict__ out) {
    extern __shared__ char sm[];
    const uint32_t smb = smem_u32(sm);
    float* const sp = reinterpret_cast<float*>(sm);
    float* const qs = sp;                 // [112][66]
    float* const ks = sp + MTQ * 66;      // [128][66]
    float* const vs = ks + MA * 66;       // [128][66]

    const int tid  = threadIdx.x;
    const int wid  = tid >> 5;
    const int lane = tid & 31;
    const int wmm  = wid >> 2;       // 0..1  (m-warp, 64 rows)
    const int wn   = wid & 3;        // 0..3  (n-warp, 48 cols)
    const int m0   = blockIdx.x * MTQ;

    float acc[4][6][4];
    #pragma unroll
    for (int mt = 0; mt < 4; mt++)
        #pragma unroll
        for (int nt = 0; nt < 6; nt++)
            #pragma unroll
            for (int q = 0; q < 4; q++) acc[mt][nt][q] = 0.f;

    const int a_row  = (lane & 15);
    const int a_col  = (lane >> 4) * 8;
    const int b_rowo = ((lane >> 4) << 3) + (lane & 7);
    const int b_col  = ((lane >> 3) & 1) * 8;

    // x loader: 128 rows x 16 float4 = 2048 -> 8 per thread
    float4 xf[8];
    auto load_x = [&](int k0) {
        #pragma unroll
        for (int l = 0; l < 8; l++) {
            int idx = l * NT + tid;
            int row = idx >> 4, c4 = idx & 15;
            int gr = m0 - 16 + row;
            gr = gr < 0 ? 0 : (gr >= NROWS ? NROWS - 1 : gr);
            xf[l] = *reinterpret_cast<const float4*>(
                x + (size_t)gr * CDIM + k0 + c4 * 4);
        }
    };
    auto store_x = [&](char* stp) {
        #pragma unroll
        for (int l = 0; l < 8; l++) {
            int idx = l * NT + tid;
            int row = idx >> 4, c4 = idx & 15;
            uint2 hp = make_uint2(pack_h2(xf[l].x, xf[l].y), pack_h2(xf[l].z, xf[l].w));
            *reinterpret_cast<uint2*>(stp + OFF_A + (uint32_t)(row * SA + c4 * 4) * 2) = hp;
        }
    };
    // B loader: 192 rows x 8 16B-units = 1536 -> 6 per thread
    auto issue_b = [&](uint32_t stn, int k0) {
        #pragma unroll
        for (int l = 0; l < 6; l++) {
            int idx = l * NT + tid;
            int n = idx >> 3, u = idx & 7;
            uint32_t so = (uint32_t)(n * SA) * 2 + u * 16;
            CP_ASYNC16(stn + OFF_B + so, g_wh + (size_t)n * CDIM + k0 + u * 8);
        }
        CP_COMMIT();
    };

    // ---- prologue ----
    load_x(0);
    issue_b(smb, 0);
    store_x(sm);
    CP_WAIT0();
    __syncthreads();

    for (int c = 0; c < NCH; c++) {
        const int s = c & 1;
        const uint32_t st = smb + s * STAGE;
        const bool more = (c + 1 < NCH);

        if (more) {
            load_x((c + 1) * BK);
            issue_b(smb + (s ^ 1) * STAGE, (c + 1) * BK);
        }

        #pragma unroll
        for (int ksp = 0; ksp < 4; ksp++) {
            const int k0h = ksp * 16;
            uint32_t ah[4][4], bf[3][4];
            #pragma unroll
            for (int mt = 0; mt < 4; mt++) {
                uint32_t ao = (uint32_t)((wmm * 64 + mt * 16 + a_row) * SA + k0h + a_col) * 2;
                ldm_x4(ah[mt], st + OFF_A + ao);
            }
            #pragma unroll
            for (int g = 0; g < 3; g++) {
                uint32_t bo = (uint32_t)((wn * 48 + g * 16 + b_rowo) * SA + k0h + b_col) * 2;
                ldm_x4(bf[g], st + OFF_B + bo);
            }
            #pragma unroll
            for (int mt = 0; mt < 4; mt++)
                #pragma unroll
                for (int g = 0; g < 3; g++) {
                    mma_f16(acc[mt][2 * g],     ah[mt], &bf[g][0]);
                    mma_f16(acc[mt][2 * g + 1], ah[mt], &bf[g][2]);
                }
        }

        if (more) {
            store_x(sm + (s ^ 1) * STAGE);
            CP_WAIT0();
            __syncthreads();
        }
    }

    // ---- scatter fragments into attention smem layout (scalar stores) ----
    __syncthreads();
    {
        const int grp = lane >> 2, tig = lane & 3;
        #pragma unroll
        for (int mt = 0; mt < 4; mt++) {
            #pragma unroll
            for (int nt = 0; nt < 6; nt++) {
                const int col = wn * 48 + nt * 8 + tig * 2;
                const int cm = col & 63;
                const int ho = (cm < 32) ? cm : cm + 1;    // padded half offset
                #pragma unroll
                for (int half = 0; half < 2; half++) {
                    const int row = wmm * 64 + mt * 16 + grp + half * 8;
                    float v0 = acc[mt][nt][half * 2];
                    float v1 = acc[mt][nt][half * 2 + 1];
                    if (col < 64) {
                        if (row >= 16) {
                            float* p = qs + (row - 16) * 66 + ho;
                            p[0] = v0; p[1] = v1;
                        }
                    } else if (col < 128) {
                        float* p = ks + row * 66 + ho;
                        p[0] = v0; p[1] = v1;
                    } else {
                        float* p = vs + row * 66 + ho;
                        p[0] = v0; p[1] = v1;
                    }
                }
            }
        }
    }
    __syncthreads();

    // ---- attention: warps 0..6, 16 queries x 2 dim-halves per warp ----
    if (wid < 7) {
        const int qi = wid * 16 + (lane & 15);     // 0..111
        const int h  = lane >> 4;
        const int d0 = h * 32;
        const int gq = m0 + qi;                    // global query row
        const int i  = gq & (SEQ - 1);             // batch-local position

        float q[32];
        {
            const float* qp = qs + qi * 66 + h * 33;
            #pragma unroll
            for (int cc = 0; cc < 32; cc++) q[cc] = qp[cc];
        }

        float sc[17];
        float mx = -1e30f;
        #pragma unroll
        for (int t = 0; t < 17; t++) {
            const float* kr = ks + (qi + t) * 66 + h * 33;
            float p0 = 0.f, p1 = 0.f, p2 = 0.f, p3 = 0.f;
            #pragma unroll
            for (int cc = 0; cc < 32; cc += 4) {
                p0 = fmaf(q[cc + 0], kr[cc + 0], p0);
                p1 = fmaf(q[cc + 1], kr[cc + 1], p1);
                p2 = fmaf(q[cc + 2], kr[cc + 2], p2);
                p3 = fmaf(q[cc + 3], kr[cc + 3], p3);
            }
            float p = (p0 + p1) + (p2 + p3);
            p += __shfl_xor_sync(0xffffffffu, p, 16);
            float d = (i - 16 + t >= 0) ? p * 0.125f : -1e30f;
            sc[t] = d;
            mx = fmaxf(mx, d);
        }

        float den = 0.f;
        #pragma unroll
        for (int t = 0; t < 17; t++) { sc[t] = __expf(sc[t] - mx); den += sc[t]; }
        const float inv = 1.0f / den;

        if (gq < NROWS) {
            float* op = out + (size_t)gq * HDIM + d0;
            #pragma unroll
            for (int cb = 0; cb < 32; cb += 4) {
                float a0 = 0.f, a1 = 0.f, a2 = 0.f, a3 = 0.f;
                #pragma unroll
                for (int t = 0; t < 17; t++) {
                    const float* vr = vs + (qi + t) * 66 + h * 33 + cb;
                    a0 = fmaf(sc[t], vr[0], a0);
                    a1 = fmaf(sc[t], vr[1], a1);
                    a2 = fmaf(sc[t], vr[2], a2);
                    a3 = fmaf(sc[t], vr[3], a3);
                }
                *reinterpret_cast<float4*>(op + cb) =
                    make_float4(a0 * inv, a1 * inv, a2 * inv, a3 * inv);
            }
        }
    }
}

// ---------------------------------------------------------------------------
extern "C" void kernel_launch(void* const* d_in, const int* in_sizes, int n_in,
                              void* d_out, int out_size)
{
    const float* x  = (const float*)d_in[0];
    const float* Wq = (const float*)d_in[1];
    const float* Wk = (const float*)d_in[2];
    const float* Wv = (const float*)d_in[3];
    float* out = (float*)d_out;

    cudaFuncSetAttribute(qkv_attn, cudaFuncAttributeMaxDynamicSharedMemorySize, FUSED_SMEM);

    const int grid = (NROWS + MTQ - 1) / MTQ;   // 147
    conv_w<<<192, 256>>>(Wq, Wk, Wv);
    qkv_attn<<<grid, NT, FUSED_SMEM>>>(x, out);
}

// round 12
// speedup vs baseline: 1.0634x; 1.0571x over previous
#include <cuda_runtime.h>
#include <cuda_fp16.h>
#include <cstdint>

#define BATCH 2
#define SEQ   8192
#define CDIM  1024
#define HDIM  64
#define NROWS (BATCH * SEQ)   // 16384
#define QKVW  (3 * HDIM)      // 192

// ---- device scratch (no allocations) --------------------------------------
__device__ __half g_wh[QKVW * CDIM];             // W^T fp16  [192][1024]

// ---- helpers ----------------------------------------------------------------
__device__ __forceinline__ uint32_t smem_u32(const void* p) {
    uint32_t a;
    asm("{ .reg .u64 t; cvta.to.shared.u64 t, %1; cvt.u32.u64 %0, t; }"
        : "=r"(a) : "l"(p));
    return a;
}
__device__ __forceinline__ void ldm_x4(uint32_t* r, uint32_t addr) {
    asm volatile("ldmatrix.sync.aligned.m8n8.x4.shared.b16 {%0,%1,%2,%3}, [%4];"
        : "=r"(r[0]), "=r"(r[1]), "=r"(r[2]), "=r"(r[3]) : "r"(addr));
}
__device__ __forceinline__ void mma_f16(float* c, const uint32_t* a, const uint32_t* b) {
    asm volatile("mma.sync.aligned.m16n8k16.row.col.f32.f16.f16.f32 "
        "{%0,%1,%2,%3}, {%4,%5,%6,%7}, {%8,%9}, {%0,%1,%2,%3};"
        : "+f"(c[0]), "+f"(c[1]), "+f"(c[2]), "+f"(c[3])
        : "r"(a[0]), "r"(a[1]), "r"(a[2]), "r"(a[3]), "r"(b[0]), "r"(b[1]));
}
#define CP_ASYNC16(sm, gm) \
    asm volatile("cp.async.cg.shared.global [%0], [%1], 16;" :: "r"(sm), "l"(gm) : "memory")
#define CP_COMMIT() asm volatile("cp.async.commit_group;" ::: "memory")
#define CP_WAIT0()  asm volatile("cp.async.wait_group 0;" ::: "memory")

__device__ __forceinline__ uint32_t pack_h2(float a, float b) {
    __half2 t = __floats2half2_rn(a, b);
    return *reinterpret_cast<uint32_t*>(&t);
}

// ---------------------------------------------------------------------------
// Pre-pass: W fp32 [1024][64] x3  ->  W^T fp16 [192][1024]
// 96 CTAs x 512 thr (single wave): 32-row k tiles, smem transpose.
// ---------------------------------------------------------------------------
__global__ __launch_bounds__(512)
void conv_w(const float* __restrict__ Wq,
            const float* __restrict__ Wk,
            const float* __restrict__ Wv) {
    __shared__ float ts[32][65];
    const int mat = blockIdx.x >> 5;          // 0..2
    const int k0  = (blockIdx.x & 31) * 32;   // k tile
    const float* W = (mat == 0) ? Wq : ((mat == 1) ? Wk : Wv);
    const int tid = threadIdx.x;

    const int ln = tid & 63, lk = tid >> 6;   // 0..7
    #pragma unroll
    for (int i = 0; i < 4; i++)
        ts[lk + i * 8][ln] = W[(size_t)(k0 + lk + i * 8) * 64 + ln];
    __syncthreads();

    const int n = tid >> 3, kq = (tid & 7) * 4;
    __half* hd = g_wh + (size_t)(mat * 64 + n) * CDIM + k0 + kq;
    __half2 a = __floats2half2_rn(ts[kq + 0][n], ts[kq + 1][n]);
    __half2 b = __floats2half2_rn(ts[kq + 2][n], ts[kq + 3][n]);
    *reinterpret_cast<__half2*>(hd)     = a;
    *reinterpret_cast<__half2*>(hd + 2) = b;
}

// ---------------------------------------------------------------------------
// Fused QKV GEMM + windowed attention.
// 112 queries per CTA; A tile = 128 rows [m0-16, m0+112) clamped. N=192.
// BK=128 (8 chunks): 192 MMAs/warp per sync window. 8 warps: 2m x 4n (64x48).
// x loaded/converted in two half-chunk waves to cap registers.
// ---------------------------------------------------------------------------
#define MTQ  112              // queries per CTA
#define MA   128              // A tile rows (16 halo + 112)
#define BK   128
#define NCH  (CDIM / BK)      // 8 chunks
#define NT   256              // threads
#define SA   136              // A/B smem row stride in halfs (272 B)
#define OFF_A  0
#define OFF_B  (MA * SA * 2)                       // 34816
#define STAGE  (OFF_B + QKVW * SA * 2)             // 87040
// attention overlay (floats): qs[112*66] | ks[128*66] | vs[128*66]
#define ATT_FLOATS ((MTQ + MA + MA) * 66)          // 24288
#define FUSED_SMEM (ATT_FLOATS * 4 > 2 * STAGE ? ATT_FLOATS * 4 : 2 * STAGE)  // 174080

__global__ __launch_bounds__(NT, 1)
void qkv_attn(const float* __restrict__ x, float* __restrict__ out) {
    extern __shared__ char sm[];
    const uint32_t smb = smem_u32(sm);
    float* const sp = reinterpret_cast<float*>(sm);
    float* const qs = sp;                 // [112][66]
    float* const ks = sp + MTQ * 66;      // [128][66]
    float* const vs = ks + MA * 66;       // [128][66]

    const int tid  = threadIdx.x;
    const int wid  = tid >> 5;
    const int lane = tid & 31;
    const int wmm  = wid >> 2;       // 0..1  (m-warp, 64 rows)
    const int wn   = wid & 3;        // 0..3  (n-warp, 48 cols)
    const int m0   = blockIdx.x * MTQ;

    float acc[4][6][4];
    #pragma unroll
    for (int mt = 0; mt < 4; mt++)
        #pragma unroll
        for (int nt = 0; nt < 6; nt++)
            #pragma unroll
            for (int q = 0; q < 4; q++) acc[mt][nt][q] = 0.f;

    const int a_row  = (lane & 15);
    const int a_col  = (lane >> 4) * 8;
    const int b_rowo = ((lane >> 4) << 3) + (lane & 7);
    const int b_col  = ((lane >> 3) & 1) * 8;

    // x half-chunk loader: 128 rows x 64 k (16 float4/row) = 2048 -> 8/thread
    float4 xf[8];
    auto load_x = [&](int k0) {       // k0 = global k of this 64-wide half
        #pragma unroll
        for (int l = 0; l < 8; l++) {
            int idx = l * NT + tid;
            int row = idx >> 4, c4 = idx & 15;
            int gr = m0 - 16 + row;
            gr = gr < 0 ? 0 : (gr >= NROWS ? NROWS - 1 : gr);
            xf[l] = *reinterpret_cast<const float4*>(
                x + (size_t)gr * CDIM + k0 + c4 * 4);
        }
    };
    auto store_x = [&](char* stp, int half) {   // half: 0 -> k 0..63, 1 -> 64..127
        #pragma unroll
        for (int l = 0; l < 8; l++) {
            int idx = l * NT + tid;
            int row = idx >> 4, c4 = idx & 15;
            uint2 hp = make_uint2(pack_h2(xf[l].x, xf[l].y), pack_h2(xf[l].z, xf[l].w));
            *reinterpret_cast<uint2*>(
                stp + OFF_A + (uint32_t)(row * SA + half * 64 + c4 * 4) * 2) = hp;
        }
    };
    // B loader: 192 rows x 16 16B-units = 3072 -> 12 per thread
    auto issue_b = [&](uint32_t stn, int k0) {
        #pragma unroll
        for (int l = 0; l < 12; l++) {
            int idx = l * NT + tid;
            int n = idx >> 4, u = idx & 15;
            uint32_t so = (uint32_t)(n * SA) * 2 + u * 16;
            CP_ASYNC16(stn + OFF_B + so, g_wh + (size_t)n * CDIM + k0 + u * 8);
        }
        CP_COMMIT();
    };

    // one 4-kstep compute half (ksteps base..base+3)
    auto compute4 = [&](uint32_t st, int base) {
        #pragma unroll
        for (int ksp = 0; ksp < 4; ksp++) {
            const int k0h = (base + ksp) * 16;
            uint32_t ah[4][4], bf[3][4];
            #pragma unroll
            for (int mt = 0; mt < 4; mt++) {
                uint32_t ao = (uint32_t)((wmm * 64 + mt * 16 + a_row) * SA + k0h + a_col) * 2;
                ldm_x4(ah[mt], st + OFF_A + ao);
            }
            #pragma unroll
            for (int g = 0; g < 3; g++) {
                uint32_t bo = (uint32_t)((wn * 48 + g * 16 + b_rowo) * SA + k0h + b_col) * 2;
                ldm_x4(bf[g], st + OFF_B + bo);
            }
            #pragma unroll
            for (int mt = 0; mt < 4; mt++)
                #pragma unroll
                for (int g = 0; g < 3; g++) {
                    mma_f16(acc[mt][2 * g],     ah[mt], &bf[g][0]);
                    mma_f16(acc[mt][2 * g + 1], ah[mt], &bf[g][2]);
                }
        }
    };

    // ---- prologue: fill stage 0 ----
    load_x(0);
    issue_b(smb, 0);
    store_x(sm, 0);
    load_x(64);
    store_x(sm, 1);
    CP_WAIT0();
    __syncthreads();

    for (int c = 0; c < NCH; c++) {
        const int s = c & 1;
        const uint32_t st = smb + s * STAGE;
        char* const stn_p = sm + (s ^ 1) * STAGE;
        const bool more = (c + 1 < NCH);

        if (more) {
            load_x((c + 1) * BK);                      // first half of next chunk
            issue_b(smb + (s ^ 1) * STAGE, (c + 1) * BK);
        }

        compute4(st, 0);                               // ksteps 0..3

        if (more) {
            store_x(stn_p, 0);
            load_x((c + 1) * BK + 64);                 // second half of next chunk
        }

        compute4(st, 4);                               // ksteps 4..7

        if (more) {
            store_x(stn_p, 1);
            CP_WAIT0();
            __syncthreads();
        }
    }

    // ---- scatter fragments into attention smem layout (scalar stores) ----
    __syncthreads();
    {
        const int grp = lane >> 2, tig = lane & 3;
        #pragma unroll
        for (int mt = 0; mt < 4; mt++) {
            #pragma unroll
            for (int nt = 0; nt < 6; nt++) {
                const int col = wn * 48 + nt * 8 + tig * 2;
                const int cm = col & 63;
                const int ho = (cm < 32) ? cm : cm + 1;    // padded half offset
                #pragma unroll
                for (int half = 0; half < 2; half++) {
                    const int row = wmm * 64 + mt * 16 + grp + half * 8;
                    float v0 = acc[mt][nt][half * 2];
                    float v1 = acc[mt][nt][half * 2 + 1];
                    if (col < 64) {
                        if (row >= 16) {
                            float* p = qs + (row - 16) * 66 + ho;
                            p[0] = v0; p[1] = v1;
                        }
                    } else if (col < 128) {
                        float* p = ks + row * 66 + ho;
                        p[0] = v0; p[1] = v1;
                    } else {
                        float* p = vs + row * 66 + ho;
                        p[0] = v0; p[1] = v1;
                    }
                }
            }
        }
    }
    __syncthreads();

    // ---- attention: warps 0..6, 16 queries x 2 dim-halves per warp ----
    if (wid < 7) {
        const int qi = wid * 16 + (lane & 15);     // 0..111
        const int h  = lane >> 4;
        const int d0 = h * 32;
        const int gq = m0 + qi;                    // global query row
        const int i  = gq & (SEQ - 1);             // batch-local position

        float q[32];
        {
            const float* qp = qs + qi * 66 + h * 33;
            #pragma unroll
            for (int cc = 0; cc < 32; cc++) q[cc] = qp[cc];
        }

        float sc[17];
        float mx = -1e30f;
        #pragma unroll
        for (int t = 0; t < 17; t++) {
            const float* kr = ks + (qi + t) * 66 + h * 33;
            float p0 = 0.f, p1 = 0.f, p2 = 0.f, p3 = 0.f;
            #pragma unroll
            for (int cc = 0; cc < 32; cc += 4) {
                p0 = fmaf(q[cc + 0], kr[cc + 0], p0);
                p1 = fmaf(q[cc + 1], kr[cc + 1], p1);
                p2 = fmaf(q[cc + 2], kr[cc + 2], p2);
                p3 = fmaf(q[cc + 3], kr[cc + 3], p3);
            }
            float p = (p0 + p1) + (p2 + p3);
            p += __shfl_xor_sync(0xffffffffu, p, 16);
            float d = (i - 16 + t >= 0) ? p * 0.125f : -1e30f;
            sc[t] = d;
            mx = fmaxf(mx, d);
        }

        float den = 0.f;
        #pragma unroll
        for (int t = 0; t < 17; t++) { sc[t] = __expf(sc[t] - mx); den += sc[t]; }
        const float inv = 1.0f / den;

        if (gq < NROWS) {
            float* op = out + (size_t)gq * HDIM + d0;
            #pragma unroll
            for (int cb = 0; cb < 32; cb += 4) {
                float a0 = 0.f, a1 = 0.f, a2 = 0.f, a3 = 0.f;
                #pragma unroll
                for (int t = 0; t < 17; t++) {
                    const float* vr = vs + (qi + t) * 66 + h * 33 + cb;
                    a0 = fmaf(sc[t], vr[0], a0);
                    a1 = fmaf(sc[t], vr[1], a1);
                    a2 = fmaf(sc[t], vr[2], a2);
                    a3 = fmaf(sc[t], vr[3], a3);
                }
                *reinterpret_cast<float4*>(op + cb) =
                    make_float4(a0 * inv, a1 * inv, a2 * inv, a3 * inv);
            }
        }
    }
}

// ---------------------------------------------------------------------------
extern "C" void kernel_launch(void* const* d_in, const int* in_sizes, int n_in,
                              void* d_out, int out_size)
{
    const float* x  = (const float*)d_in[0];
    const float* Wq = (const float*)d_in[1];
    const float* Wk = (const float*)d_in[2];
    const float* Wv = (const float*)d_in[3];
    float* out = (float*)d_out;

    cudaFuncSetAttribute(qkv_attn, cudaFuncAttributeMaxDynamicSharedMemorySize, FUSED_SMEM);

    const int grid = (NROWS + MTQ - 1) / MTQ;   // 147
    conv_w<<<96, 512>>>(Wq, Wk, Wv);
    qkv_attn<<<grid, NT, FUSED_SMEM>>>(x, out);
}